// round 14
// baseline (speedup 1.0000x reference)
#include <cuda_runtime.h>
#include <cstdint>

// EmbeddingDropout: out[r, :] = weight[x[r], :] * rowmask(x[r])
// rowmask: bit-exact jax.random.bernoulli(jax.random.key(42), 0.9, (50257,1))
// under the partitionable threefry path (JAX >= 0.4.30 default):
//   (o0,o1) = threefry2x32(key=(0,42), (hi32(v)=0, lo32(v)=v)); bits = o0^o1
//   u = bitcast((bits>>9)|0x3f800000) - 1.0f;  keep = u < 0.9f; scale = keep/0.9
// x indices arrive as int32 (JAX x64-disabled demotes jnp.int64 -> int32).
//
// R13: full TMA datapath. Rows staged via cp.async.bulk gmem->smem (mbarrier
// transaction-counted), scaled in smem, written back via cp.async.bulk
// smem->gmem with an L2 evict_first policy (preserves the R12 streaming-store
// win). Eliminates per-thread STG.128 issue cost (12cyc each) and lifts
// in-flight read bytes from ~3KB/SM (register MLP) to ~128KB/SM (TMA).

#define TF_ROUND(r) { x0 += x1; x1 = (x1 << (r)) | (x1 >> (32 - (r))); x1 ^= x0; }

__device__ __forceinline__ float row_scale(uint32_t v)
{
    const uint32_t k0 = 0u;
    const uint32_t k1 = 42u;
    const uint32_t k2 = 0u ^ 42u ^ 0x1BD11BDAu;

    uint32_t x0 = 0u;   // hi32 of uint64 counter
    uint32_t x1 = v;    // lo32

    x0 += k0; x1 += k1;
    TF_ROUND(13) TF_ROUND(15) TF_ROUND(26) TF_ROUND(6)
    x0 += k1; x1 += k2 + 1u;
    TF_ROUND(17) TF_ROUND(29) TF_ROUND(16) TF_ROUND(24)
    x0 += k2; x1 += k0 + 2u;
    TF_ROUND(13) TF_ROUND(15) TF_ROUND(26) TF_ROUND(6)
    x0 += k0; x1 += k1 + 3u;
    TF_ROUND(17) TF_ROUND(29) TF_ROUND(16) TF_ROUND(24)
    x0 += k1; x1 += k2 + 4u;
    TF_ROUND(13) TF_ROUND(15) TF_ROUND(26) TF_ROUND(6)
    x0 += k2; x1 += k0 + 5u;

    uint32_t bits = x0 ^ x1;

    float u = __uint_as_float((bits >> 9) | 0x3f800000u) - 1.0f;
    return (u < 0.9f) ? (1.0f / 0.9f) : 0.0f;
}

__device__ __forceinline__ uint32_t smem_u32(const void* p)
{
    uint32_t a;
    asm("{ .reg .u64 t; cvta.to.shared.u64 t, %1; cvt.u32.u64 %0, t; }"
        : "=r"(a) : "l"(p));
    return a;
}

__device__ __forceinline__ int clamp_idx(int i)
{
    return (i < 0) ? 0 : ((i > 50256) ? 50256 : i);
}

// 4 rows per CTA, 256 threads. Row bytes = 4096.
__global__ void __launch_bounds__(256, 8)
embedding_dropout_kernel(const int* __restrict__ x,
                         const float* __restrict__ weight,
                         float* __restrict__ out)
{
    __shared__ alignas(1024) float buf[4][1024];   // 16 KB
    __shared__ alignas(8) uint64_t mbar;

    const int tid = threadIdx.x;
    const uint32_t mbar_a = smem_u32(&mbar);

    if (tid == 0) {
        asm volatile("mbarrier.init.shared.b64 [%0], %1;"
                     :: "r"(mbar_a), "r"(4u) : "memory");
    }
    __syncthreads();

    // --- Producer: 4 bulk loads (one per row), each thread arrives+expects
    //     its own 4096 bytes. Barrier flips after 4 arrivals + 16KB tx. ---
    if (tid < 4) {
        const int row = (blockIdx.x << 2) + tid;
        const int idx = clamp_idx(x[row]);
        const float* src = weight + (long long)idx * 1024ll;
        const uint32_t dst = smem_u32(&buf[tid][0]);

        asm volatile("mbarrier.arrive.expect_tx.shared.b64 _, [%0], %1;"
                     :: "r"(mbar_a), "r"(4096u) : "memory");
        asm volatile(
            "cp.async.bulk.shared::cluster.global.mbarrier::complete_tx::bytes "
            "[%0], [%1], %2, [%3];"
            :: "r"(dst), "l"(src), "r"(4096u), "r"(mbar_a) : "memory");
    }

    // --- All threads wait for the tile (acquire orders the LDS below). ---
    {
        uint32_t done;
        asm volatile(
            "{\n\t.reg .pred p;\n\t"
            "mbarrier.try_wait.parity.acquire.cta.shared::cta.b64 p, [%1], %2;\n\t"
            "selp.b32 %0, 1, 0, p;\n\t}"
            : "=r"(done) : "r"(mbar_a), "r"(0u) : "memory");
        if (!done) {
            asm volatile(
                "{\n\t.reg .pred P1;\n\t"
                "W_%=:\n\t"
                "mbarrier.try_wait.parity.acquire.cta.shared::cta.b64 P1, [%0], %1, 0x989680;\n\t"
                "@P1 bra.uni D_%=;\n\t"
                "bra.uni W_%=;\n\t"
                "D_%=:\n\t}"
                :: "r"(mbar_a), "r"(0u) : "memory");
        }
    }

    // --- Scale in smem: 64 threads per row, 4 float4s each. ---
    {
        const int sub = tid >> 6;          // 0..3: row within CTA
        const int t   = tid & 63;          // 0..63
        const int row = (blockIdx.x << 2) + sub;
        const int idx = clamp_idx(x[row]);
        const float s = row_scale((uint32_t)idx);

        float4* p = reinterpret_cast<float4*>(&buf[sub][0]) + t;
        float4 v0 = p[0];
        float4 v1 = p[64];
        float4 v2 = p[128];
        float4 v3 = p[192];
        v0.x *= s; v0.y *= s; v0.z *= s; v0.w *= s;
        v1.x *= s; v1.y *= s; v1.z *= s; v1.w *= s;
        v2.x *= s; v2.y *= s; v2.z *= s; v2.w *= s;
        v3.x *= s; v3.y *= s; v3.z *= s; v3.w *= s;
        p[0]   = v0;
        p[64]  = v1;
        p[128] = v2;
        p[192] = v3;
    }

    // Make generic-proxy smem writes visible to the async (bulk-copy) proxy.
    asm volatile("fence.proxy.async.shared::cta;" ::: "memory");
    __syncthreads();

    // --- Consumer: 4 bulk stores smem->gmem, evict_first L2 policy. ---
    if (tid < 4) {
        const int row = (blockIdx.x << 2) + tid;
        float* dst = out + (long long)row * 1024ll;
        const uint32_t src = smem_u32(&buf[tid][0]);

        uint64_t pol;
        asm volatile("createpolicy.fractional.L2::evict_first.b64 %0, 1.0;"
                     : "=l"(pol));
        asm volatile(
            "cp.async.bulk.global.shared::cta.bulk_group.L2::cache_hint "
            "[%0], [%1], %2, %3;"
            :: "l"(dst), "r"(src), "r"(4096u), "l"(pol) : "memory");
        asm volatile("cp.async.bulk.commit_group;" ::: "memory");
        asm volatile("cp.async.bulk.wait_group 0;" ::: "memory");
    }
}

extern "C" void kernel_launch(void* const* d_in, const int* in_sizes, int n_in,
                              void* d_out, int out_size)
{
    // Robust to input ordering: x has 16,384 elements, weight has 51,463,168.
    int xi = 0, wi = 1;
    if (n_in >= 2 && in_sizes[0] > in_sizes[1]) { xi = 1; wi = 0; }

    const int* x = (const int*)d_in[xi];          // int32 [8,2048]
    const float* weight = (const float*)d_in[wi]; // f32 [50257,1024]
    float* out = (float*)d_out;                   // f32 [8,2048,1024]

    const int n_rows = in_sizes[xi];              // 16384 (divisible by 4)
    embedding_dropout_kernel<<<n_rows / 4, 256>>>(x, weight, out);
}